// round 6
// baseline (speedup 1.0000x reference)
#include <cuda_runtime.h>
#include <math.h>

#define NN    2048
#define BG    8
#define NODES (NN*BG)
#define KNNK  4
#define INC   16
#define HIDD  128
#define NC    64
#define EMAX  262144

// ---------------- scratch (no allocs allowed) ----------------
__device__ float g_y  [NODES*HIDD];   // xw1 (UNscaled)
__device__ float g_h1 [NODES*HIDD];
__device__ float g_xw2[NODES*HIDD];
__device__ float g_h2 [NODES*HIDD];
__device__ float g_coord[3*NODES];
__device__ float g_pool[BG*NC*HIDD];
__device__ float g_ss [BG*NC*NC];
__device__ float g_ca [BG*NC];
__device__ float g_ssum[BG*NC];
__device__ float g_tr [BG];
__device__ int   g_cnt [NODES];
__device__ int   g_rowptr[NODES];
__device__ int   g_pos [NODES];
__device__ int   g_eidx[EMAX];
__device__ int   g_ecnt[BG];
__device__ int   g_knn [NODES*KNNK];

// ---------------- kernels ----------------
__global__ void k_zero() {
    int i = blockIdx.x*blockDim.x + threadIdx.x;
    if (i < NODES) g_cnt[i] = 0;
    if (i < BG*NC*HIDD) g_pool[i] = 0.f;
    if (i < BG*NC*NC) g_ss[i] = 0.f;
    if (i < BG*NC) { g_ca[i] = 0.f; g_ssum[i] = 0.f; }
    if (i < BG) { g_ecnt[i] = 0; g_tr[i] = 0.f; }
}

__global__ void k_hist(const int* __restrict__ src, const int* __restrict__ dst, int E) {
    int e = blockIdx.x*blockDim.x + threadIdx.x;
    if (e < E) {
        atomicAdd(&g_cnt[dst[e]], 1);
        atomicAdd(&g_ecnt[src[e]/NN], 1);
    }
}

// exclusive prefix sum of g_cnt -> g_rowptr, g_pos (one block, 1024 thr, 16 each)
__global__ void k_scan() {
    __shared__ int wsum[32];
    int t = threadIdx.x, lane = t & 31, w = t >> 5;
    int base = t*16;
    int loc[16]; int s = 0;
#pragma unroll
    for (int i = 0; i < 16; i++) { loc[i] = s; s += g_cnt[base + i]; }
    int v = s;
#pragma unroll
    for (int o = 1; o < 32; o <<= 1) { int u = __shfl_up_sync(~0u, v, o); if (lane >= o) v += u; }
    if (lane == 31) wsum[w] = v;
    __syncthreads();
    if (w == 0) {
        int u = wsum[lane];
#pragma unroll
        for (int o = 1; o < 32; o <<= 1) { int x = __shfl_up_sync(~0u, u, o); if (lane >= o) u += x; }
        wsum[lane] = u;
    }
    __syncthreads();
    int excl = v - s + (w ? wsum[w-1] : 0);
#pragma unroll
    for (int i = 0; i < 16; i++) { int off = excl + loc[i]; g_rowptr[base+i] = off; g_pos[base+i] = off; }
}

__global__ void k_fill(const int* __restrict__ src, const int* __restrict__ dst, int E) {
    int e = blockIdx.x*blockDim.x + threadIdx.x;
    if (e < E) {
        int p = atomicAdd(&g_pos[dst[e]], 1);
        g_eidx[p] = src[e];
    }
}

// xw1 = x @ W1 (UNscaled) — 16 nodes/block, W1 staged in smem. Independent of edges.
__global__ void k_xw1(const float* __restrict__ x, const float* __restrict__ W1) {
    __shared__ float w1s[INC*HIDD];
    __shared__ float xs[16*INC];
    int t = threadIdx.x;
    for (int i = t; i < INC*HIDD; i += 128) w1s[i] = W1[i];
    int n0 = blockIdx.x*16;
    for (int i = t; i < 16*INC; i += 128) xs[i] = x[n0*INC + i];
    __syncthreads();
#pragma unroll
    for (int r = 0; r < 16; r++) {
        float a = 0.f;
#pragma unroll
        for (int k = 0; k < INC; k++) a += xs[r*INC + k] * w1s[k*HIDD + t];
        g_y[(n0 + r)*HIDD + t] = a;
    }
}

// GCN1 gather with per-src weights: h1 = relu(rsn*(y[n]*rsn_self + sum y[src]*w[src]) + b1)
__global__ void k_gcn1(const float* __restrict__ b1) {
    __shared__ int   idxs[512];
    __shared__ float wts [512];
    int n = blockIdx.x, c = threadIdx.x;
    int beg = g_rowptr[n], cnt = g_cnt[n];
    int lim = cnt < 512 ? cnt : 512;
    for (int i = c; i < lim; i += HIDD) {
        int idx = g_eidx[beg + i];
        idxs[i] = idx;
        wts[i]  = rsqrtf((float)(g_cnt[idx] + 1));
    }
    __syncthreads();
    float rsn = rsqrtf((float)(cnt + 1));
    float acc = g_y[n*HIDD + c] * rsn;
#pragma unroll 4
    for (int i = 0; i < lim; i++) acc += g_y[idxs[i]*HIDD + c] * wts[i];
    for (int i = 512; i < cnt; i++) {
        int idx = g_eidx[beg + i];
        acc += g_y[idx*HIDD + c] * rsqrtf((float)(g_cnt[idx] + 1));
    }
    float v = fmaxf(acc * rsn + b1[c], 0.f);
    g_h1[n*HIDD + c] = v;
    if (c < 3) g_coord[c*NODES + n] = v;
}

// kNN (K=4); grid (BG, NN/128), 128 thr
__global__ void k_knn() {
    __shared__ float cx[NN], cy[NN], cz[NN];
    int b = blockIdx.x, base = b*NN;
    for (int j = threadIdx.x; j < NN; j += blockDim.x) {
        cx[j] = g_coord[0*NODES + base + j];
        cy[j] = g_coord[1*NODES + base + j];
        cz[j] = g_coord[2*NODES + base + j];
    }
    __syncthreads();
    int i = blockIdx.y*blockDim.x + threadIdx.x;
    float xi = cx[i], yi = cy[i], zi = cz[i];
    float bd[KNNK]; int bi[KNNK];
#pragma unroll
    for (int t = 0; t < KNNK; t++) { bd[t] = 1e30f; bi[t] = NN; }
    for (int j = 0; j < NN; j++) {
        if (j == i) continue;
        float dx = xi - cx[j], dy = yi - cy[j], dz = zi - cz[j];
        float d2 = dx*dx + dy*dy + dz*dz;
        if (d2 < bd[3]) {
            bd[3] = d2; bi[3] = j;
#pragma unroll
            for (int t = 3; t > 0; t--) {
                if (bd[t] < bd[t-1]) {
                    float td = bd[t]; bd[t] = bd[t-1]; bd[t-1] = td;
                    int ti = bi[t]; bi[t] = bi[t-1]; bi[t-1] = ti;
                }
            }
        }
    }
#pragma unroll
    for (int t = 0; t < KNNK; t++) g_knn[(base + i)*KNNK + t] = base + bi[t];
}

// xw2 = h1 @ W2 — 32 rows per block, float4 A reads
__global__ void k_xw2(const float* __restrict__ W2) {
    __shared__ __align__(16) float As[32*HIDD];
    int r0 = blockIdx.x * 32, c = threadIdx.x;
    for (int r = 0; r < 32; r++) As[r*HIDD + c] = g_h1[(r0 + r)*HIDD + c];
    __syncthreads();
    float acc[32];
#pragma unroll
    for (int r = 0; r < 32; r++) acc[r] = 0.f;
    for (int k = 0; k < HIDD; k += 4) {
        float b0 = W2[(k+0)*HIDD + c], b1 = W2[(k+1)*HIDD + c];
        float b2 = W2[(k+2)*HIDD + c], b3 = W2[(k+3)*HIDD + c];
#pragma unroll
        for (int r = 0; r < 32; r++) {
            float4 a = *(const float4*)&As[r*HIDD + k];
            acc[r] += a.x*b0 + a.y*b1 + a.z*b2 + a.w*b3;
        }
    }
    for (int r = 0; r < 32; r++) g_xw2[(r0 + r)*HIDD + c] = acc[r];
}

// GCN2: deg==5 -> norm 1/5
__global__ void k_gcn2(const float* __restrict__ b2) {
    int n = blockIdx.x, c = threadIdx.x;
    const float nf = 0.2f;
    int k0 = g_knn[n*KNNK+0], k1 = g_knn[n*KNNK+1], k2 = g_knn[n*KNNK+2], k3 = g_knn[n*KNNK+3];
    float v = (g_xw2[n*HIDD+c] + g_xw2[k0*HIDD+c] + g_xw2[k1*HIDD+c]
             + g_xw2[k2*HIDD+c] + g_xw2[k3*HIDD+c]) * nf + b2[c];
    g_h2[n*HIDD + c] = fmaxf(v, 0.f);
}

// s = softmax(h2 @ Wp + bp); 8 nodes/block, 512 thr, Wp staged in smem
#define SNODES 8
__global__ void k_s(const float* __restrict__ Wp, const float* __restrict__ bp,
                    float* __restrict__ sout) {
    __shared__ float wps[HIDD*NC];
    __shared__ float hr[SNODES][HIDD];
    __shared__ float red[SNODES][NC];
    int t = threadIdx.x;
    int n0 = blockIdx.x * SNODES;
    for (int i = t; i < HIDD*NC; i += 512) wps[i] = Wp[i];
    for (int i = t; i < SNODES*HIDD; i += 512) hr[i >> 7][i & 127] = g_h2[n0*HIDD + i];
    __syncthreads();
    int r = t >> 6, c = t & 63;
    float a = bp[c];
#pragma unroll 8
    for (int k = 0; k < HIDD; k++) a = fmaf(hr[r][k], wps[k*NC + c], a);
    red[r][c] = a;
    __syncthreads();
    for (int o = 32; o; o >>= 1) { if (c < o) red[r][c] = fmaxf(red[r][c], red[r][c+o]); __syncthreads(); }
    float mx = red[r][0]; __syncthreads();
    float e = expf(a - mx);
    red[r][c] = e;
    __syncthreads();
    for (int o = 32; o; o >>= 1) { if (c < o) red[r][c] += red[r][c+o]; __syncthreads(); }
    sout[(n0 + r)*NC + c] = e / red[r][0];
}

// pooled[b,c,f] += partial; grid (8,8,4), 128 thr
__global__ void k_pool(const float* __restrict__ s) {
    __shared__ float ssm[128][9];
    int b = blockIdx.x, cg = blockIdx.y, ch = blockIdx.z, f = threadIdx.x;
    int base = b*NN + ch*(NN/4);
    float acc[8];
#pragma unroll
    for (int j = 0; j < 8; j++) acc[j] = 0.f;
    for (int nt = 0; nt < NN/4; nt += 128) {
#pragma unroll
        for (int j = 0; j < 8; j++) ssm[f][j] = s[(base + nt + f)*NC + cg*8 + j];
        __syncthreads();
#pragma unroll 4
        for (int nn = 0; nn < 128; nn++) {
            float xv = g_h2[(base + nt + nn)*HIDD + f];
#pragma unroll
            for (int j = 0; j < 8; j++) acc[j] += ssm[nn][j] * xv;
        }
        __syncthreads();
    }
#pragma unroll
    for (int j = 0; j < 8; j++) atomicAdd(&g_pool[(b*NC + cg*8 + j)*HIDD + f], acc[j]);
}

// ss[b,c,d] += partial; grid (8,8,4), 64 thr
__global__ void k_ssk(const float* __restrict__ s) {
    __shared__ float ssm[128][9];
    int b = blockIdx.x, cg = blockIdx.y, ch = blockIdx.z, d = threadIdx.x;
    int base = b*NN + ch*(NN/4);
    float acc[8];
#pragma unroll
    for (int j = 0; j < 8; j++) acc[j] = 0.f;
    for (int nt = 0; nt < NN/4; nt += 128) {
        for (int r = d; r < 128; r += NC)
#pragma unroll
            for (int j = 0; j < 8; j++) ssm[r][j] = s[(base + nt + r)*NC + cg*8 + j];
        __syncthreads();
#pragma unroll 4
        for (int nn = 0; nn < 128; nn++) {
            float xv = s[(base + nt + nn)*NC + d];
#pragma unroll
            for (int j = 0; j < 8; j++) acc[j] += ssm[nn][j] * xv;
        }
        __syncthreads();
    }
#pragma unroll
    for (int j = 0; j < 8; j++) atomicAdd(&g_ss[b*NC*NC + (cg*8 + j)*NC + d], acc[j]);
}

// ca / ssum; grid (8,16), 64 thr
__global__ void k_ca(const float* __restrict__ s) {
    int b = blockIdx.x, ch = blockIdx.y, c = threadIdx.x;
    int base = b*NN + ch*(NN/16);
    float ca = 0.f, su = 0.f;
#pragma unroll 8
    for (int n = 0; n < NN/16; n++) {
        float sv = s[(base + n)*NC + c];
        ca += sv * (float)g_cnt[base + n];
        su += sv;
    }
    atomicAdd(&g_ca[b*NC + c], ca);
    atomicAdd(&g_ssum[b*NC + c], su);
}

// trace(S^T A S); warp per edge
__global__ void k_tr(const int* __restrict__ src, const int* __restrict__ dst,
                     const float* __restrict__ s, int E) {
    __shared__ float bins[BG];
    if (threadIdx.x < BG) bins[threadIdx.x] = 0.f;
    __syncthreads();
    int warp = threadIdx.x >> 5, lane = threadIdx.x & 31;
    int gw = blockIdx.x*(blockDim.x >> 5) + warp;
    int nw = gridDim.x*(blockDim.x >> 5);
    for (int e = gw; e < E; e += nw) {
        int a = src[e], d = dst[e];
        float v = s[a*NC + lane]*s[d*NC + lane] + s[a*NC + 32 + lane]*s[d*NC + 32 + lane];
#pragma unroll
        for (int o = 16; o; o >>= 1) v += __shfl_down_sync(0xffffffffu, v, o);
        if (lane == 0) atomicAdd(&bins[a/NN], v);
    }
    __syncthreads();
    if (threadIdx.x < BG) atomicAdd(&g_tr[threadIdx.x], bins[threadIdx.x]);
}

// selu + log_softmax
__global__ void k_out(float* __restrict__ out) {
    __shared__ float red[HIDD];
    int row = blockIdx.x, f = threadIdx.x;
    float v = g_pool[row*HIDD + f];
    const float alpha = 1.6732632423543772f, scale = 1.0507009873554805f;
    v = scale * (v > 0.f ? v : alpha * expm1f(v));
    red[f] = v; __syncthreads();
    for (int o = 64; o; o >>= 1) { if (f < o) red[f] = fmaxf(red[f], red[f+o]); __syncthreads(); }
    float mx = red[0]; __syncthreads();
    float e = expf(v - mx);
    red[f] = e; __syncthreads();
    for (int o = 64; o; o >>= 1) { if (f < o) red[f] += red[f+o]; __syncthreads(); }
    float lse = logf(red[0]);
    out[row*HIDD + f] = v - mx - lse;
}

// scalar loss
__global__ void k_final(float* __restrict__ loss_out) {
    __shared__ float red[256];
    int t = threadIdx.x;
    float spectral = 0.f, ortho = 0.f, cluster = 0.f;
    for (int b = 0; b < BG; b++) {
        float p = 0.f;
        for (int i = t; i < NC*NC; i += 256) { float v = g_ss[b*NC*NC + i]; p += v*v; }
        red[t] = p; __syncthreads();
        for (int o = 128; o; o >>= 1) { if (t < o) red[t] += red[t+o]; __syncthreads(); }
        float fro = sqrtf(red[0]); __syncthreads();
        p = 0.f;
        for (int i = t; i < NC*NC; i += 256) {
            float v = g_ss[b*NC*NC + i] / fro;
            if ((i >> 6) == (i & 63)) v -= 0.125f;
            p += v*v;
        }
        red[t] = p; __syncthreads();
        for (int o = 128; o; o >>= 1) { if (t < o) red[t] += red[t+o]; __syncthreads(); }
        ortho += sqrtf(red[0]); __syncthreads();
        p = 0.f;
        for (int i = t; i < NC; i += 256) { float v = g_ca[b*NC + i]; p += v*v; }
        red[t] = p; __syncthreads();
        for (int o = 128; o; o >>= 1) { if (t < o) red[t] += red[t+o]; __syncthreads(); }
        float ca2 = red[0]; __syncthreads();
        float m = 0.5f * (float)g_ecnt[b];
        spectral += -(g_tr[b] - ca2 / (2.f*m)) / (2.f*m);
        p = 0.f;
        for (int i = t; i < NC; i += 256) { float v = g_ssum[b*NC + i]; p += v*v; }
        red[t] = p; __syncthreads();
        for (int o = 128; o; o >>= 1) { if (t < o) red[t] += red[t+o]; __syncthreads(); }
        cluster += sqrtf(red[0]) / (float)NN * 8.f - 1.f; __syncthreads();
    }
    if (t == 0)
        loss_out[0] = spectral / (float)BG + ortho / (float)BG + cluster / (float)BG;
}

// ---------------- launch (multi-stream fork/join, graph-capturable) ----------------
extern "C" void kernel_launch(void* const* d_in, const int* in_sizes, int n_in,
                              void* d_out, int out_size) {
    const float* x    = (const float*)d_in[0];
    const int*   esrc = (const int*)  d_in[1];
    const int*   edst = (const int*)  d_in[2];
    const float* W1   = (const float*)d_in[4];
    const float* b1   = (const float*)d_in[5];
    const float* W2   = (const float*)d_in[6];
    const float* b2   = (const float*)d_in[7];
    const float* Wp   = (const float*)d_in[8];
    const float* bp   = (const float*)d_in[9];
    float* out = (float*)d_out;
    int E = in_sizes[1];

    float* loss_out = out + BG*NC*HIDD;        // [65536]
    float* sout     = out + BG*NC*HIDD + 1;    // [65537 ..)

    static cudaStream_t st1 = 0, st2 = 0, st3 = 0;
    static cudaEvent_t evRoot, evX, evG, evK, evS, ev1, ev2, ev3;
    if (st1 == 0) {
        cudaStreamCreateWithFlags(&st1, cudaStreamNonBlocking);
        cudaStreamCreateWithFlags(&st2, cudaStreamNonBlocking);
        cudaStreamCreateWithFlags(&st3, cudaStreamNonBlocking);
        cudaEventCreateWithFlags(&evRoot, cudaEventDisableTiming);
        cudaEventCreateWithFlags(&evX, cudaEventDisableTiming);
        cudaEventCreateWithFlags(&evG, cudaEventDisableTiming);
        cudaEventCreateWithFlags(&evK, cudaEventDisableTiming);
        cudaEventCreateWithFlags(&evS, cudaEventDisableTiming);
        cudaEventCreateWithFlags(&ev1, cudaEventDisableTiming);
        cudaEventCreateWithFlags(&ev2, cudaEventDisableTiming);
        cudaEventCreateWithFlags(&ev3, cudaEventDisableTiming);
    }

    // fork root: st1 branches off before the edge pipeline
    cudaEventRecord(evRoot, 0);
    cudaStreamWaitEvent(st1, evRoot, 0);

    // st1: xw1 (independent of edges)
    k_xw1<<<NODES/16, 128, 0, st1>>>(x, W1);
    cudaEventRecord(evX, st1);

    // main: zero -> hist -> scan -> fill
    k_zero<<<(BG*NC*HIDD + 255)/256, 256>>>();
    k_hist<<<(E + 255)/256, 256>>>(esrc, edst, E);
    k_scan<<<1, 1024>>>();
    k_fill<<<(E + 255)/256, 256>>>(esrc, edst, E);

    // join xw1, then gather
    cudaStreamWaitEvent(0, evX, 0);
    k_gcn1<<<NODES, HIDD>>>(b1);
    cudaEventRecord(evG, 0);

    // st1: knn (overlaps xw2 on main)
    cudaStreamWaitEvent(st1, evG, 0);
    dim3 kg(BG, NN/128);
    k_knn<<<kg, 128, 0, st1>>>();
    cudaEventRecord(evK, st1);

    // main: xw2, then join knn -> gcn2 -> s
    k_xw2<<<NODES/32, HIDD>>>(W2);
    cudaStreamWaitEvent(0, evK, 0);
    k_gcn2<<<NODES, HIDD>>>(b2);
    k_s<<<NODES/SNODES, 512>>>(Wp, bp, sout);
    cudaEventRecord(evS, 0);

    // stats fan-out: pool on main; ssk/ca/tr on side streams
    cudaStreamWaitEvent(st1, evS, 0);
    cudaStreamWaitEvent(st2, evS, 0);
    cudaStreamWaitEvent(st3, evS, 0);
    dim3 pg(BG, 8, 4);
    k_pool<<<pg, HIDD>>>(sout);
    k_ssk<<<pg, NC, 0, st1>>>(sout);
    dim3 cg(BG, 16);
    k_ca<<<cg, NC, 0, st2>>>(sout);
    k_tr<<<2048, 256, 0, st3>>>(esrc, edst, sout, E);

    // main: out (after pool)
    k_out<<<BG*NC, HIDD>>>(out);

    // join all, final loss
    cudaEventRecord(ev1, st1);
    cudaEventRecord(ev2, st2);
    cudaEventRecord(ev3, st3);
    cudaStreamWaitEvent(0, ev1, 0);
    cudaStreamWaitEvent(0, ev2, 0);
    cudaStreamWaitEvent(0, ev3, 0);
    k_final<<<1, 256>>>(loss_out);
}